// round 16
// baseline (speedup 1.0000x reference)
#include <cuda_runtime.h>
#include <cuda_bf16.h>
#include <cstdint>

// ---------------- problem constants ----------------
#define B_SZ 16384
#define P_N  128
#define V_N  128
#define W_N  64
#define BN_EPS 1e-5

// ---------------- scratch (static device globals; no allocation) ----------------
__device__ __nv_bfloat16  g_p[P_N * B_SZ];          // p[pathway][batch], bf16, 4 MB
__device__ __nv_bfloat16  g_W1bf[P_N * W_N * V_N];  // bf16 W1, row-major [p][w][v], 2 MB
__device__ double         g_S1[P_N], g_S2[P_N];
__device__ float          g_a[P_N];
__device__ float          g_c;
__device__ unsigned int   g_tick = 0;               // k2a completion ticket

__device__ __forceinline__ uint32_t smem_u32(const void* p) {
    uint32_t a;
    asm("{ .reg .u64 t; cvta.to.shared.u64 t, %1; cvt.u32.u64 %0, t; }" : "=r"(a) : "l"(p));
    return a;
}

// swizzled byte offset inside a [rows][128 bf16] tile (256 B per row)
__device__ __forceinline__ int swz(int row, int byte_in_row) {
    return row * 256 + (byte_in_row ^ ((row & 7) << 4));
}

__device__ __forceinline__ void ldmatrix_x4(uint32_t& r0, uint32_t& r1, uint32_t& r2, uint32_t& r3,
                                            uint32_t addr) {
    asm volatile("ldmatrix.sync.aligned.m8n8.x4.shared.b16 {%0,%1,%2,%3}, [%4];"
                 : "=r"(r0), "=r"(r1), "=r"(r2), "=r"(r3) : "r"(addr));
}

__device__ __forceinline__ void mma_bf16(float& c0, float& c1, float& c2, float& c3,
                                         uint32_t a0, uint32_t a1, uint32_t a2, uint32_t a3,
                                         uint32_t b0, uint32_t b1) {
    asm volatile("mma.sync.aligned.m16n8k16.row.col.f32.bf16.bf16.f32 "
                 "{%0,%1,%2,%3}, {%4,%5,%6,%7}, {%8,%9}, {%0,%1,%2,%3};"
                 : "+f"(c0), "+f"(c1), "+f"(c2), "+f"(c3)
                 : "r"(a0), "r"(a1), "r"(a2), "r"(a3), "r"(b0), "r"(b1));
}

// ============ K0: convert W1 fp32 -> bf16 row-major ============
__global__ __launch_bounds__(256) void k0_w1bf(const float* __restrict__ W1) {
    int idx = blockIdx.x * 256 + threadIdx.x;      // < 262144, each handles 4 elems
    float4 v = *reinterpret_cast<const float4*>(W1 + (size_t)idx * 4);
    __nv_bfloat162 lo = __float22bfloat162_rn(make_float2(v.x, v.y));
    __nv_bfloat162 hi = __float22bfloat162_rn(make_float2(v.z, v.w));
    uint2 pack = make_uint2(*reinterpret_cast<uint32_t*>(&lo), *reinterpret_cast<uint32_t*>(&hi));
    *reinterpret_cast<uint2*>(g_W1bf + (size_t)idx * 4) = pack;
}

// ============ K1: per-pathway [128x64x128] bf16 mma.sync, 4 warps x (32x64) tiles ============
// (byte-identical to R15)
__global__ __launch_bounds__(128, 4) void k1_mma(const float* __restrict__ x,
                                                 const float* __restrict__ W2) {
    extern __shared__ char smem[];                 // [0,32768) xs swizzled, [32768,49152) ws swizzled
    const uint32_t sb = smem_u32(smem);
    const int tid = threadIdx.x;
    const int wid = tid >> 5;
    const int lid = tid & 31;
    const int rb = blockIdx.x;                     // 128-row batch block
    const int p  = blockIdx.y;                     // pathway

    // ---- copy W1 bf16 tile first: 64 rows x 128 -> swizzled smem, then CTA barrier ----
    {
        const uint4* wsrc = reinterpret_cast<const uint4*>(g_W1bf + (size_t)p * (W_N * V_N));
        #pragma unroll
        for (int i = 0; i < 8; i++) {
            int idx = tid + i * 128;               // < 1024 16B-chunks
            int n = idx >> 4;
            int kc = idx & 15;
            *reinterpret_cast<uint4*>(smem + 32768 + swz(n, kc * 16)) = wsrc[idx];
        }
    }
    __syncthreads();

    const int m0 = wid * 32;

    // ---- per-warp x staging: this warp's 32 rows x 128 fp32 -> bf16 swizzled smem ----
    {
        const float* xrow = x + (size_t)(rb * 128 + m0) * (P_N * V_N) + (size_t)p * V_N;
        #pragma unroll
        for (int i = 0; i < 32; i++) {
            int idx = lid + i * 32;                // < 1024
            int r = idx >> 5;                      // 0..31 local row
            int c = (idx & 31);                    // float4 index in row
            float4 v = *reinterpret_cast<const float4*>(xrow + (size_t)r * (P_N * V_N) + c * 4);
            __nv_bfloat162 lo = __float22bfloat162_rn(make_float2(v.x, v.y));
            __nv_bfloat162 hi = __float22bfloat162_rn(make_float2(v.z, v.w));
            uint2 pack = make_uint2(*reinterpret_cast<uint32_t*>(&lo), *reinterpret_cast<uint32_t*>(&hi));
            *reinterpret_cast<uint2*>(smem + swz(m0 + r, c * 8)) = pack;
        }
    }
    __syncwarp();

    // ---- mainloop: warp computes [32 x 64], K=128 ----
    float acc[2][8][4];                             // [m16-frag][n8-frag][quad]
    #pragma unroll
    for (int m = 0; m < 2; m++)
        #pragma unroll
        for (int t = 0; t < 8; t++)
            #pragma unroll
            for (int j = 0; j < 4; j++) acc[m][t][j] = 0.f;

    const uint32_t a_row = m0 + (lid & 15);
    const uint32_t a_chunk = (lid >> 4) * 16;
    const int bg = lid >> 3;                        // 0..3 address group
    const int b_nrow_off = (lid & 7) + ((bg >= 2) ? 8 : 0);
    const int b_koff = (bg & 1) * 16;

    #pragma unroll
    for (int ks = 0; ks < 8; ks++) {
        const int kb = ks * 32;                     // byte offset of k-step in row
        uint32_t a00, a01, a02, a03;                // rows [m0, m0+16)
        uint32_t a10, a11, a12, a13;                // rows [m0+16, m0+32)
        ldmatrix_x4(a00, a01, a02, a03, sb + swz(a_row, kb + a_chunk));
        ldmatrix_x4(a10, a11, a12, a13, sb + swz(a_row + 16, kb + a_chunk));
        #pragma unroll
        for (int t = 0; t < 4; t++) {
            uint32_t b0, b1, b2, b3;
            ldmatrix_x4(b0, b1, b2, b3,
                        sb + 32768 + swz(t * 16 + b_nrow_off, kb + b_koff));
            mma_bf16(acc[0][2*t][0], acc[0][2*t][1], acc[0][2*t][2], acc[0][2*t][3],
                     a00, a01, a02, a03, b0, b1);
            mma_bf16(acc[0][2*t+1][0], acc[0][2*t+1][1], acc[0][2*t+1][2], acc[0][2*t+1][3],
                     a00, a01, a02, a03, b2, b3);
            mma_bf16(acc[1][2*t][0], acc[1][2*t][1], acc[1][2*t][2], acc[1][2*t][3],
                     a10, a11, a12, a13, b0, b1);
            mma_bf16(acc[1][2*t+1][0], acc[1][2*t+1][1], acc[1][2*t+1][2], acc[1][2*t+1][3],
                     a10, a11, a12, a13, b2, b3);
        }
    }

    // ---- epilogue: h=leaky(acc); dot with W2 over n; p=leaky(dot); store bf16 ----
    {
        const float2* w2p = reinterpret_cast<const float2*>(W2 + (size_t)p * W_N);
        float s00 = 0.f, s01 = 0.f;                 // m-frag 0: rows (lid>>2), (lid>>2)+8
        float s10 = 0.f, s11 = 0.f;                 // m-frag 1: +16
        #pragma unroll
        for (int t = 0; t < 8; t++) {
            float2 w2v = __ldg(&w2p[t * 4 + (lid & 3)]);   // cols t*8 + (lid&3)*2, +1
            float h;
            h = acc[0][t][0]; h = (h >= 0.f) ? h : 0.2f * h; s00 += h * w2v.x;
            h = acc[0][t][1]; h = (h >= 0.f) ? h : 0.2f * h; s00 += h * w2v.y;
            h = acc[0][t][2]; h = (h >= 0.f) ? h : 0.2f * h; s01 += h * w2v.x;
            h = acc[0][t][3]; h = (h >= 0.f) ? h : 0.2f * h; s01 += h * w2v.y;
            h = acc[1][t][0]; h = (h >= 0.f) ? h : 0.2f * h; s10 += h * w2v.x;
            h = acc[1][t][1]; h = (h >= 0.f) ? h : 0.2f * h; s10 += h * w2v.y;
            h = acc[1][t][2]; h = (h >= 0.f) ? h : 0.2f * h; s11 += h * w2v.x;
            h = acc[1][t][3]; h = (h >= 0.f) ? h : 0.2f * h; s11 += h * w2v.y;
        }
        s00 += __shfl_xor_sync(0xFFFFFFFF, s00, 1);
        s00 += __shfl_xor_sync(0xFFFFFFFF, s00, 2);
        s01 += __shfl_xor_sync(0xFFFFFFFF, s01, 1);
        s01 += __shfl_xor_sync(0xFFFFFFFF, s01, 2);
        s10 += __shfl_xor_sync(0xFFFFFFFF, s10, 1);
        s10 += __shfl_xor_sync(0xFFFFFFFF, s10, 2);
        s11 += __shfl_xor_sync(0xFFFFFFFF, s11, 1);
        s11 += __shfl_xor_sync(0xFFFFFFFF, s11, 2);
        if ((lid & 3) == 0) {
            int row = lid >> 2;
            float pv00 = (s00 >= 0.f) ? s00 : 0.2f * s00;
            float pv01 = (s01 >= 0.f) ? s01 : 0.2f * s01;
            float pv10 = (s10 >= 0.f) ? s10 : 0.2f * s10;
            float pv11 = (s11 >= 0.f) ? s11 : 0.2f * s11;
            __nv_bfloat16* dst = g_p + (size_t)p * B_SZ + rb * 128 + m0;
            dst[row]      = __float2bfloat16_rn(pv00);
            dst[row + 8]  = __float2bfloat16_rn(pv01);
            dst[row + 16] = __float2bfloat16_rn(pv10);
            dst[row + 24] = __float2bfloat16_rn(pv11);
        }
    }
}

// ============ K2a: per-pathway sum / sumsq + last-block finalize of a_p, c ============
__global__ __launch_bounds__(256) void k2a_reduce(const float* __restrict__ gamma,
                                                  const float* __restrict__ beta,
                                                  const float* __restrict__ Wd,
                                                  const float* __restrict__ bdp) {
    const int p = blockIdx.x;
    const int tid = threadIdx.x;
    const uint4* col = reinterpret_cast<const uint4*>(g_p + (size_t)p * B_SZ);  // 8 bf16 per uint4
    float a0 = 0.f, a1 = 0.f, a2 = 0.f, a3 = 0.f;
    float q0 = 0.f, q1 = 0.f, q2 = 0.f, q3 = 0.f;
    #pragma unroll 4
    for (int i = tid; i < B_SZ / 8; i += 256) {
        uint4 v = col[i];
        float2 f0 = __bfloat1622float2(*reinterpret_cast<__nv_bfloat162*>(&v.x));
        float2 f1 = __bfloat1622float2(*reinterpret_cast<__nv_bfloat162*>(&v.y));
        float2 f2 = __bfloat1622float2(*reinterpret_cast<__nv_bfloat162*>(&v.z));
        float2 f3 = __bfloat1622float2(*reinterpret_cast<__nv_bfloat162*>(&v.w));
        a0 += f0.x + f0.y; a1 += f1.x + f1.y; a2 += f2.x + f2.y; a3 += f3.x + f3.y;
        q0 = fmaf(f0.x, f0.x, q0); q0 = fmaf(f0.y, f0.y, q0);
        q1 = fmaf(f1.x, f1.x, q1); q1 = fmaf(f1.y, f1.y, q1);
        q2 = fmaf(f2.x, f2.x, q2); q2 = fmaf(f2.y, f2.y, q2);
        q3 = fmaf(f3.x, f3.x, q3); q3 = fmaf(f3.y, f3.y, q3);
    }
    double s1v = (double)a0 + (double)a1 + (double)a2 + (double)a3;
    double s2v = (double)q0 + (double)q1 + (double)q2 + (double)q3;
    __shared__ double s1[256], s2[256];
    s1[tid] = s1v; s2[tid] = s2v;
    __syncthreads();
    for (int o = 128; o > 0; o >>= 1) {
        if (tid < o) { s1[tid] += s1[tid + o]; s2[tid] += s2[tid + o]; }
        __syncthreads();
    }
    __shared__ unsigned int ticket;
    if (tid == 0) {
        g_S1[p] = s1[0]; g_S2[p] = s2[0];
        __threadfence();
        ticket = atomicAdd(&g_tick, 1u);
    }
    __syncthreads();

    // ---- last-finishing block computes the projection coefficients ----
    if (ticket == P_N - 1) {
        __threadfence();
        __shared__ float sw[128];
        __shared__ float sn[128], st[128];
        if (tid < 128) {
            const int pp = tid;
            const double invB = 1.0 / (double)B_SZ;
            double mean_d = g_S1[pp] * invB;
            double var_d = g_S2[pp] * invB - mean_d * mean_d;
            float var = (float)(var_d < 0.0 ? 0.0 : var_d);
            float mean = (float)mean_d;
            float sig2 = var + (float)BN_EPS;
            float inv_sigma = rsqrtf(sig2);
            float g = gamma[pp], bt = beta[pp], wd = Wd[pp];
            sn[pp] = g * g * (float)B_SZ * var / sig2 + (float)B_SZ * bt * bt;
            st[pp] = (bt - mean * g * inv_sigma) * wd;
            sw[pp] = g * wd * inv_sigma;
        }
        __syncthreads();
        for (int o = 64; o > 0; o >>= 1) {
            if (tid < o) { sn[tid] += sn[tid + o]; st[tid] += st[tid + o]; }
            __syncthreads();
        }
        if (tid < 128) {
            float inv_norm = rsqrtf(sn[0]);
            g_a[tid] = sw[tid] * inv_norm;
            if (tid == 0) {
                g_c = st[0] * inv_norm + bdp[0];
                g_tick = 0u;                        // reset for next graph replay
            }
        }
    }
}

// ============ K3: coefficients from g_a + wide loads + sigmoid(dot + c) ============
__global__ __launch_bounds__(256) void k3_out(float* __restrict__ out) {
    __shared__ float sa[128];
    __shared__ float sc_s;
    const int tid = threadIdx.x;

    // ---- issue data loads first ----
    const int gid = blockIdx.x * 256 + tid;
    const int q = gid & 31;                // pathway chunk (4 pathways)
    const int t = gid >> 5;                // 4-batch group index (0..4095)
    const uint2* pp = reinterpret_cast<const uint2*>(g_p);   // 4 bf16 per uint2
    uint2 u0 = pp[(size_t)(q * 4 + 0) * (B_SZ / 4) + t];
    uint2 u1 = pp[(size_t)(q * 4 + 1) * (B_SZ / 4) + t];
    uint2 u2 = pp[(size_t)(q * 4 + 2) * (B_SZ / 4) + t];
    uint2 u3 = pp[(size_t)(q * 4 + 3) * (B_SZ / 4) + t];

    if (tid < 128) sa[tid] = g_a[tid];
    if (tid == 0) sc_s = g_c;
    __syncthreads();
    const float sc = sc_s;

    // ---- dot + butterfly + sigmoid ----
    float a0 = sa[q * 4 + 0], a1 = sa[q * 4 + 1], a2 = sa[q * 4 + 2], a3 = sa[q * 4 + 3];
    float2 l0 = __bfloat1622float2(*reinterpret_cast<__nv_bfloat162*>(&u0.x));
    float2 h0 = __bfloat1622float2(*reinterpret_cast<__nv_bfloat162*>(&u0.y));
    float2 l1 = __bfloat1622float2(*reinterpret_cast<__nv_bfloat162*>(&u1.x));
    float2 h1 = __bfloat1622float2(*reinterpret_cast<__nv_bfloat162*>(&u1.y));
    float2 l2 = __bfloat1622float2(*reinterpret_cast<__nv_bfloat162*>(&u2.x));
    float2 h2 = __bfloat1622float2(*reinterpret_cast<__nv_bfloat162*>(&u2.y));
    float2 l3 = __bfloat1622float2(*reinterpret_cast<__nv_bfloat162*>(&u3.x));
    float2 h3 = __bfloat1622float2(*reinterpret_cast<__nv_bfloat162*>(&u3.y));
    float4 acc;
    acc.x = l0.x * a0 + l1.x * a1 + l2.x * a2 + l3.x * a3;
    acc.y = l0.y * a0 + l1.y * a1 + l2.y * a2 + l3.y * a3;
    acc.z = h0.x * a0 + h1.x * a1 + h2.x * a2 + h3.x * a3;
    acc.w = h0.y * a0 + h1.y * a1 + h2.y * a2 + h3.y * a3;
    #pragma unroll
    for (int m = 1; m < 32; m <<= 1) {
        acc.x += __shfl_xor_sync(0xFFFFFFFF, acc.x, m);
        acc.y += __shfl_xor_sync(0xFFFFFFFF, acc.y, m);
        acc.z += __shfl_xor_sync(0xFFFFFFFF, acc.z, m);
        acc.w += __shfl_xor_sync(0xFFFFFFFF, acc.w, m);
    }
    if (q == 0) {
        float4 o;
        o.x = 1.f / (1.f + expf(-(acc.x + sc)));
        o.y = 1.f / (1.f + expf(-(acc.y + sc)));
        o.z = 1.f / (1.f + expf(-(acc.z + sc)));
        o.w = 1.f / (1.f + expf(-(acc.w + sc)));
        reinterpret_cast<float4*>(out)[t] = o;
    }
}

// ============ launch ============
extern "C" void kernel_launch(void* const* d_in, const int* in_sizes, int n_in,
                              void* d_out, int out_size) {
    const float* x     = (const float*)d_in[0];
    const float* W1    = (const float*)d_in[1];
    const float* W2    = (const float*)d_in[2];
    const float* gamma = (const float*)d_in[3];
    const float* beta  = (const float*)d_in[4];
    const float* Wd    = (const float*)d_in[5];
    const float* bdp   = (const float*)d_in[6];
    float* out = (float*)d_out;

    k0_w1bf<<<1024, 256>>>(W1);
    k1_mma<<<dim3(B_SZ / 128, P_N), 128, 49152>>>(x, W2);
    k2a_reduce<<<P_N, 256>>>(gamma, beta, Wd, bdp);
    k3_out<<<512, 256>>>(out);
}

// round 17
// speedup vs baseline: 1.0151x; 1.0151x over previous
#include <cuda_runtime.h>
#include <cuda_bf16.h>
#include <cstdint>

// ---------------- problem constants ----------------
#define B_SZ 16384
#define P_N  128
#define V_N  128
#define W_N  64
#define BN_EPS 1e-5

// ---------------- scratch (static device globals; no allocation) ----------------
__device__ __nv_bfloat16  g_p[P_N * B_SZ];          // p[pathway][batch], bf16, 4 MB
__device__ __nv_bfloat16  g_W1bf[P_N * W_N * V_N];  // bf16 W1, row-major [p][w][v], 2 MB
__device__ double         g_S1[P_N], g_S2[P_N];

__device__ __forceinline__ uint32_t smem_u32(const void* p) {
    uint32_t a;
    asm("{ .reg .u64 t; cvta.to.shared.u64 t, %1; cvt.u32.u64 %0, t; }" : "=r"(a) : "l"(p));
    return a;
}

// swizzled byte offset inside a [rows][128 bf16] tile (256 B per row)
__device__ __forceinline__ int swz(int row, int byte_in_row) {
    return row * 256 + (byte_in_row ^ ((row & 7) << 4));
}

__device__ __forceinline__ void ldmatrix_x4(uint32_t& r0, uint32_t& r1, uint32_t& r2, uint32_t& r3,
                                            uint32_t addr) {
    asm volatile("ldmatrix.sync.aligned.m8n8.x4.shared.b16 {%0,%1,%2,%3}, [%4];"
                 : "=r"(r0), "=r"(r1), "=r"(r2), "=r"(r3) : "r"(addr));
}

__device__ __forceinline__ void mma_bf16(float& c0, float& c1, float& c2, float& c3,
                                         uint32_t a0, uint32_t a1, uint32_t a2, uint32_t a3,
                                         uint32_t b0, uint32_t b1) {
    asm volatile("mma.sync.aligned.m16n8k16.row.col.f32.bf16.bf16.f32 "
                 "{%0,%1,%2,%3}, {%4,%5,%6,%7}, {%8,%9}, {%0,%1,%2,%3};"
                 : "+f"(c0), "+f"(c1), "+f"(c2), "+f"(c3)
                 : "r"(a0), "r"(a1), "r"(a2), "r"(a3), "r"(b0), "r"(b1));
}

// ============ K0: convert W1 fp32 -> bf16 row-major ============
__global__ __launch_bounds__(256) void k0_w1bf(const float* __restrict__ W1) {
    int idx = blockIdx.x * 256 + threadIdx.x;      // < 262144, each handles 4 elems
    float4 v = *reinterpret_cast<const float4*>(W1 + (size_t)idx * 4);
    __nv_bfloat162 lo = __float22bfloat162_rn(make_float2(v.x, v.y));
    __nv_bfloat162 hi = __float22bfloat162_rn(make_float2(v.z, v.w));
    uint2 pack = make_uint2(*reinterpret_cast<uint32_t*>(&lo), *reinterpret_cast<uint32_t*>(&hi));
    *reinterpret_cast<uint2*>(g_W1bf + (size_t)idx * 4) = pack;
}

// ============ K1: per-pathway [128x64x128] bf16 mma.sync, 4 warps x (32x64) tiles ============
// x staging issued FIRST (DRAM loads start at CTA entry), then the L2-resident W1 copy,
// then one barrier covering both. A-fragments are warp-local so no extra sync needed.
__global__ __launch_bounds__(128, 4) void k1_mma(const float* __restrict__ x,
                                                 const float* __restrict__ W2) {
    extern __shared__ char smem[];                 // [0,32768) xs swizzled, [32768,49152) ws swizzled
    const uint32_t sb = smem_u32(smem);
    const int tid = threadIdx.x;
    const int wid = tid >> 5;
    const int lid = tid & 31;
    const int rb = blockIdx.x;                     // 128-row batch block
    const int p  = blockIdx.y;                     // pathway

    const int m0 = wid * 32;

    // ---- per-warp x staging FIRST: 32 rows x 128 fp32 -> bf16 swizzled smem ----
    {
        const float* xrow = x + (size_t)(rb * 128 + m0) * (P_N * V_N) + (size_t)p * V_N;
        #pragma unroll
        for (int i = 0; i < 32; i++) {
            int idx = lid + i * 32;                // < 1024
            int r = idx >> 5;                      // 0..31 local row
            int c = (idx & 31);                    // float4 index in row
            float4 v = *reinterpret_cast<const float4*>(xrow + (size_t)r * (P_N * V_N) + c * 4);
            __nv_bfloat162 lo = __float22bfloat162_rn(make_float2(v.x, v.y));
            __nv_bfloat162 hi = __float22bfloat162_rn(make_float2(v.z, v.w));
            uint2 pack = make_uint2(*reinterpret_cast<uint32_t*>(&lo), *reinterpret_cast<uint32_t*>(&hi));
            *reinterpret_cast<uint2*>(smem + swz(m0 + r, c * 8)) = pack;
        }
    }
    // ---- copy W1 bf16 tile: 64 rows x 128 -> swizzled smem ----
    {
        const uint4* wsrc = reinterpret_cast<const uint4*>(g_W1bf + (size_t)p * (W_N * V_N));
        #pragma unroll
        for (int i = 0; i < 8; i++) {
            int idx = tid + i * 128;               // < 1024 16B-chunks
            int n = idx >> 4;
            int kc = idx & 15;
            *reinterpret_cast<uint4*>(smem + 32768 + swz(n, kc * 16)) = wsrc[idx];
        }
    }
    __syncthreads();                               // covers W1 (CTA-wide) and own-warp x stores

    // ---- mainloop: warp computes [32 x 64], K=128 ----
    float acc[2][8][4];                             // [m16-frag][n8-frag][quad]
    #pragma unroll
    for (int m = 0; m < 2; m++)
        #pragma unroll
        for (int t = 0; t < 8; t++)
            #pragma unroll
            for (int j = 0; j < 4; j++) acc[m][t][j] = 0.f;

    const uint32_t a_row = m0 + (lid & 15);
    const uint32_t a_chunk = (lid >> 4) * 16;
    const int bg = lid >> 3;                        // 0..3 address group
    const int b_nrow_off = (lid & 7) + ((bg >= 2) ? 8 : 0);
    const int b_koff = (bg & 1) * 16;

    #pragma unroll
    for (int ks = 0; ks < 8; ks++) {
        const int kb = ks * 32;                     // byte offset of k-step in row
        uint32_t a00, a01, a02, a03;                // rows [m0, m0+16)
        uint32_t a10, a11, a12, a13;                // rows [m0+16, m0+32)
        ldmatrix_x4(a00, a01, a02, a03, sb + swz(a_row, kb + a_chunk));
        ldmatrix_x4(a10, a11, a12, a13, sb + swz(a_row + 16, kb + a_chunk));
        #pragma unroll
        for (int t = 0; t < 4; t++) {
            uint32_t b0, b1, b2, b3;
            ldmatrix_x4(b0, b1, b2, b3,
                        sb + 32768 + swz(t * 16 + b_nrow_off, kb + b_koff));
            mma_bf16(acc[0][2*t][0], acc[0][2*t][1], acc[0][2*t][2], acc[0][2*t][3],
                     a00, a01, a02, a03, b0, b1);
            mma_bf16(acc[0][2*t+1][0], acc[0][2*t+1][1], acc[0][2*t+1][2], acc[0][2*t+1][3],
                     a00, a01, a02, a03, b2, b3);
            mma_bf16(acc[1][2*t][0], acc[1][2*t][1], acc[1][2*t][2], acc[1][2*t][3],
                     a10, a11, a12, a13, b0, b1);
            mma_bf16(acc[1][2*t+1][0], acc[1][2*t+1][1], acc[1][2*t+1][2], acc[1][2*t+1][3],
                     a10, a11, a12, a13, b2, b3);
        }
    }

    // ---- epilogue: h=leaky(acc); dot with W2 over n; p=leaky(dot); store bf16 ----
    {
        const float2* w2p = reinterpret_cast<const float2*>(W2 + (size_t)p * W_N);
        float s00 = 0.f, s01 = 0.f;                 // m-frag 0: rows (lid>>2), (lid>>2)+8
        float s10 = 0.f, s11 = 0.f;                 // m-frag 1: +16
        #pragma unroll
        for (int t = 0; t < 8; t++) {
            float2 w2v = __ldg(&w2p[t * 4 + (lid & 3)]);   // cols t*8 + (lid&3)*2, +1
            float h;
            h = acc[0][t][0]; h = (h >= 0.f) ? h : 0.2f * h; s00 += h * w2v.x;
            h = acc[0][t][1]; h = (h >= 0.f) ? h : 0.2f * h; s00 += h * w2v.y;
            h = acc[0][t][2]; h = (h >= 0.f) ? h : 0.2f * h; s01 += h * w2v.x;
            h = acc[0][t][3]; h = (h >= 0.f) ? h : 0.2f * h; s01 += h * w2v.y;
            h = acc[1][t][0]; h = (h >= 0.f) ? h : 0.2f * h; s10 += h * w2v.x;
            h = acc[1][t][1]; h = (h >= 0.f) ? h : 0.2f * h; s10 += h * w2v.y;
            h = acc[1][t][2]; h = (h >= 0.f) ? h : 0.2f * h; s11 += h * w2v.x;
            h = acc[1][t][3]; h = (h >= 0.f) ? h : 0.2f * h; s11 += h * w2v.y;
        }
        s00 += __shfl_xor_sync(0xFFFFFFFF, s00, 1);
        s00 += __shfl_xor_sync(0xFFFFFFFF, s00, 2);
        s01 += __shfl_xor_sync(0xFFFFFFFF, s01, 1);
        s01 += __shfl_xor_sync(0xFFFFFFFF, s01, 2);
        s10 += __shfl_xor_sync(0xFFFFFFFF, s10, 1);
        s10 += __shfl_xor_sync(0xFFFFFFFF, s10, 2);
        s11 += __shfl_xor_sync(0xFFFFFFFF, s11, 1);
        s11 += __shfl_xor_sync(0xFFFFFFFF, s11, 2);
        if ((lid & 3) == 0) {
            int row = lid >> 2;
            float pv00 = (s00 >= 0.f) ? s00 : 0.2f * s00;
            float pv01 = (s01 >= 0.f) ? s01 : 0.2f * s01;
            float pv10 = (s10 >= 0.f) ? s10 : 0.2f * s10;
            float pv11 = (s11 >= 0.f) ? s11 : 0.2f * s11;
            __nv_bfloat16* dst = g_p + (size_t)p * B_SZ + rb * 128 + m0;
            dst[row]      = __float2bfloat16_rn(pv00);
            dst[row + 8]  = __float2bfloat16_rn(pv01);
            dst[row + 16] = __float2bfloat16_rn(pv10);
            dst[row + 24] = __float2bfloat16_rn(pv11);
        }
    }
}

// ============ K2a: per-pathway sum / sumsq over bf16 p (fp32 accumulators, fp64 tree) ============
__global__ __launch_bounds__(256) void k2a_reduce() {
    const int p = blockIdx.x;
    const int tid = threadIdx.x;
    const uint4* col = reinterpret_cast<const uint4*>(g_p + (size_t)p * B_SZ);  // 8 bf16 per uint4
    float a0 = 0.f, a1 = 0.f, a2 = 0.f, a3 = 0.f;
    float q0 = 0.f, q1 = 0.f, q2 = 0.f, q3 = 0.f;
    #pragma unroll 4
    for (int i = tid; i < B_SZ / 8; i += 256) {
        uint4 v = col[i];
        float2 f0 = __bfloat1622float2(*reinterpret_cast<__nv_bfloat162*>(&v.x));
        float2 f1 = __bfloat1622float2(*reinterpret_cast<__nv_bfloat162*>(&v.y));
        float2 f2 = __bfloat1622float2(*reinterpret_cast<__nv_bfloat162*>(&v.z));
        float2 f3 = __bfloat1622float2(*reinterpret_cast<__nv_bfloat162*>(&v.w));
        a0 += f0.x + f0.y; a1 += f1.x + f1.y; a2 += f2.x + f2.y; a3 += f3.x + f3.y;
        q0 = fmaf(f0.x, f0.x, q0); q0 = fmaf(f0.y, f0.y, q0);
        q1 = fmaf(f1.x, f1.x, q1); q1 = fmaf(f1.y, f1.y, q1);
        q2 = fmaf(f2.x, f2.x, q2); q2 = fmaf(f2.y, f2.y, q2);
        q3 = fmaf(f3.x, f3.x, q3); q3 = fmaf(f3.y, f3.y, q3);
    }
    double s1v = (double)a0 + (double)a1 + (double)a2 + (double)a3;
    double s2v = (double)q0 + (double)q1 + (double)q2 + (double)q3;
    __shared__ double s1[256], s2[256];
    s1[tid] = s1v; s2[tid] = s2v;
    __syncthreads();
    for (int o = 128; o > 0; o >>= 1) {
        if (tid < o) { s1[tid] += s1[tid + o]; s2[tid] += s2[tid + o]; }
        __syncthreads();
    }
    if (tid == 0) { g_S1[p] = s1[0]; g_S2[p] = s2[0]; }
}

// ============ K3: hoisted bf16 g_p loads + per-block finalize + sigmoid(dot + c) ============
__global__ __launch_bounds__(256) void k3_out(float* __restrict__ out,
                                              const float* __restrict__ gamma,
                                              const float* __restrict__ beta,
                                              const float* __restrict__ Wd,
                                              const float* __restrict__ bdp) {
    __shared__ float sa[128];
    __shared__ float sw[128];
    __shared__ float sn[128], st[128];
    __shared__ float sc_s;
    const int tid = threadIdx.x;

    // ---- issue data loads first (independent of coefficients) ----
    const int gid = blockIdx.x * 256 + tid;
    const int q = gid & 31;                // pathway chunk (4 pathways)
    const int t = gid >> 5;                // 4-batch group index (0..4095)
    const uint2* pp = reinterpret_cast<const uint2*>(g_p);   // 4 bf16 per uint2
    uint2 u0 = pp[(size_t)(q * 4 + 0) * (B_SZ / 4) + t];
    uint2 u1 = pp[(size_t)(q * 4 + 1) * (B_SZ / 4) + t];
    uint2 u2 = pp[(size_t)(q * 4 + 2) * (B_SZ / 4) + t];
    uint2 u3 = pp[(size_t)(q * 4 + 3) * (B_SZ / 4) + t];

    // ---- in-block finalize (threads 0..127) while loads are in flight ----
    if (tid < 128) {
        const int p = tid;
        const double invB = 1.0 / (double)B_SZ;
        double mean_d = g_S1[p] * invB;
        double var_d = g_S2[p] * invB - mean_d * mean_d;   // fp64: cancellation-sensitive
        float var = (float)(var_d < 0.0 ? 0.0 : var_d);
        float mean = (float)mean_d;
        float sig2 = var + (float)BN_EPS;
        float inv_sigma = rsqrtf(sig2);
        float g = gamma[p], bt = beta[p], wd = Wd[p];
        sn[p] = g * g * (float)B_SZ * var / sig2 + (float)B_SZ * bt * bt;
        st[p] = (bt - mean * g * inv_sigma) * wd;
        sw[p] = g * wd * inv_sigma;
    }
    __syncthreads();
    for (int o = 64; o > 0; o >>= 1) {
        if (tid < o) { sn[tid] += sn[tid + o]; st[tid] += st[tid + o]; }
        __syncthreads();
    }
    if (tid < 128) {
        float inv_norm = rsqrtf(sn[0]);
        sa[tid] = sw[tid] * inv_norm;
        if (tid == 0) sc_s = st[0] * inv_norm + bdp[0];
    }
    __syncthreads();
    const float sc = sc_s;

    // ---- dot + butterfly + sigmoid ----
    float a0 = sa[q * 4 + 0], a1 = sa[q * 4 + 1], a2 = sa[q * 4 + 2], a3 = sa[q * 4 + 3];
    float2 l0 = __bfloat1622float2(*reinterpret_cast<__nv_bfloat162*>(&u0.x));
    float2 h0 = __bfloat1622float2(*reinterpret_cast<__nv_bfloat162*>(&u0.y));
    float2 l1 = __bfloat1622float2(*reinterpret_cast<__nv_bfloat162*>(&u1.x));
    float2 h1 = __bfloat1622float2(*reinterpret_cast<__nv_bfloat162*>(&u1.y));
    float2 l2 = __bfloat1622float2(*reinterpret_cast<__nv_bfloat162*>(&u2.x));
    float2 h2 = __bfloat1622float2(*reinterpret_cast<__nv_bfloat162*>(&u2.y));
    float2 l3 = __bfloat1622float2(*reinterpret_cast<__nv_bfloat162*>(&u3.x));
    float2 h3 = __bfloat1622float2(*reinterpret_cast<__nv_bfloat162*>(&u3.y));
    float4 acc;
    acc.x = l0.x * a0 + l1.x * a1 + l2.x * a2 + l3.x * a3;
    acc.y = l0.y * a0 + l1.y * a1 + l2.y * a2 + l3.y * a3;
    acc.z = h0.x * a0 + h1.x * a1 + h2.x * a2 + h3.x * a3;
    acc.w = h0.y * a0 + h1.y * a1 + h2.y * a2 + h3.y * a3;
    #pragma unroll
    for (int m = 1; m < 32; m <<= 1) {
        acc.x += __shfl_xor_sync(0xFFFFFFFF, acc.x, m);
        acc.y += __shfl_xor_sync(0xFFFFFFFF, acc.y, m);
        acc.z += __shfl_xor_sync(0xFFFFFFFF, acc.z, m);
        acc.w += __shfl_xor_sync(0xFFFFFFFF, acc.w, m);
    }
    if (q == 0) {
        float4 o;
        o.x = 1.f / (1.f + expf(-(acc.x + sc)));
        o.y = 1.f / (1.f + expf(-(acc.y + sc)));
        o.z = 1.f / (1.f + expf(-(acc.z + sc)));
        o.w = 1.f / (1.f + expf(-(acc.w + sc)));
        reinterpret_cast<float4*>(out)[t] = o;
    }
}

// ============ launch ============
extern "C" void kernel_launch(void* const* d_in, const int* in_sizes, int n_in,
                              void* d_out, int out_size) {
    const float* x     = (const float*)d_in[0];
    const float* W1    = (const float*)d_in[1];
    const float* W2    = (const float*)d_in[2];
    const float* gamma = (const float*)d_in[3];
    const float* beta  = (const float*)d_in[4];
    const float* Wd    = (const float*)d_in[5];
    const float* bdp   = (const float*)d_in[6];
    float* out = (float*)d_out;

    k0_w1bf<<<1024, 256>>>(W1);
    k1_mma<<<dim3(B_SZ / 128, P_N), 128, 49152>>>(x, W2);
    k2a_reduce<<<P_N, 256>>>();
    k3_out<<<512, 256>>>(out, gamma, beta, Wd, bdp);
}